// round 3
// baseline (speedup 1.0000x reference)
#include <cuda_runtime.h>

#define NB 32
#define NS 8192
#define ND 64
#define NSPLIT 16
#define ROWS (NS / NSPLIT)   // 512 seq rows per CTA
#define BK 32                // rows per smem stage
#define NSTAGE (ROWS / BK)   // 16
#define BKP 36               // padded k-stride (36 mod 32 = 4 -> conflict-free frags)

// Partial results: [NSPLIT][NB][2][64][64]  (mat 0 = rr+ii, mat 1 = ri)
__device__ __align__(16) float g_scratch[NSPLIT * NB * 2 * ND * ND];

__device__ __forceinline__ unsigned f2tf(float x) {
    unsigned u;
    asm("cvt.rna.tf32.f32 %0, %1;" : "=r"(u) : "f"(x));
    return u;
}

__device__ __forceinline__ void mma_tf32(float c[4],
                                         unsigned a0, unsigned a1, unsigned a2, unsigned a3,
                                         unsigned b0, unsigned b1) {
    asm volatile(
        "mma.sync.aligned.m16n8k8.row.col.f32.tf32.tf32.f32 "
        "{%0,%1,%2,%3}, {%4,%5,%6,%7}, {%8,%9}, {%0,%1,%2,%3};"
        : "+f"(c[0]), "+f"(c[1]), "+f"(c[2]), "+f"(c[3])
        : "r"(a0), "r"(a1), "r"(a2), "r"(a3), "r"(b0), "r"(b1));
}

__global__ __launch_bounds__(128) void gram_kernel(const float* __restrict__ gr,
                                                   const float* __restrict__ gi) {
    // Transposed tiles: sX[buf][d][k], k-stride BKP=36.
    __shared__ unsigned sR[2][ND][BKP];
    __shared__ unsigned sI[2][ND][BKP];

    const int b    = blockIdx.x >> 4;           // NSPLIT = 16
    const int sp   = blockIdx.x & (NSPLIT - 1);
    const int tid  = threadIdx.x;
    const int lane = tid & 31;
    const int warp = tid >> 5;
    const int g    = lane >> 2;   // groupID
    const int t    = lane & 3;    // threadID_in_group
    const int m0   = warp * 16;   // this warp's m-band

    const float* baseR = gr + ((long)b * NS + (long)sp * ROWS) * ND;
    const float* baseI = gi + ((long)b * NS + (long)sp * ROWS) * ND;

    // Global-load mapping: lane -> seq row within stage, warp -> 16-float d segment.
    const int kloc = lane;
    const int dseg = warp * 16;

    float accR[8][4];  // rr + ii accumulators, 8 n-tiles
    float accM[8][4];  // ri accumulators
#pragma unroll
    for (int j = 0; j < 8; j++)
#pragma unroll
        for (int c = 0; c < 4; c++) { accR[j][c] = 0.0f; accM[j][c] = 0.0f; }

    float4 rv[4], iv[4];

    // ---- prologue: load + store stage 0 into buffer 0 ----
#pragma unroll
    for (int c = 0; c < 4; c++) {
        rv[c] = *(const float4*)(baseR + (long)kloc * ND + dseg + 4 * c);
        iv[c] = *(const float4*)(baseI + (long)kloc * ND + dseg + 4 * c);
    }
#pragma unroll
    for (int c = 0; c < 4; c++) {
        sR[0][dseg + 4 * c + 0][kloc] = f2tf(rv[c].x);
        sR[0][dseg + 4 * c + 1][kloc] = f2tf(rv[c].y);
        sR[0][dseg + 4 * c + 2][kloc] = f2tf(rv[c].z);
        sR[0][dseg + 4 * c + 3][kloc] = f2tf(rv[c].w);
        sI[0][dseg + 4 * c + 0][kloc] = f2tf(iv[c].x);
        sI[0][dseg + 4 * c + 1][kloc] = f2tf(iv[c].y);
        sI[0][dseg + 4 * c + 2][kloc] = f2tf(iv[c].z);
        sI[0][dseg + 4 * c + 3][kloc] = f2tf(iv[c].w);
    }
    __syncthreads();

    for (int st = 0; st < NSTAGE; st++) {
        const int cur = st & 1;
        const int nxt = cur ^ 1;

        // Prefetch next stage into registers (overlaps with MMA below).
        if (st + 1 < NSTAGE) {
            const long roff = (long)((st + 1) * BK + kloc) * ND + dseg;
#pragma unroll
            for (int c = 0; c < 4; c++) {
                rv[c] = *(const float4*)(baseR + roff + 4 * c);
                iv[c] = *(const float4*)(baseI + roff + 4 * c);
            }
        }

        // Compute current stage: 4 k8-steps.
#pragma unroll
        for (int kk = 0; kk < BK; kk += 8) {
            const unsigned ar0 = sR[cur][m0 + g    ][kk + t    ];
            const unsigned ar1 = sR[cur][m0 + g + 8][kk + t    ];
            const unsigned ar2 = sR[cur][m0 + g    ][kk + t + 4];
            const unsigned ar3 = sR[cur][m0 + g + 8][kk + t + 4];
            const unsigned ai0 = sI[cur][m0 + g    ][kk + t    ];
            const unsigned ai1 = sI[cur][m0 + g + 8][kk + t    ];
            const unsigned ai2 = sI[cur][m0 + g    ][kk + t + 4];
            const unsigned ai3 = sI[cur][m0 + g + 8][kk + t + 4];
#pragma unroll
            for (int j = 0; j < 8; j++) {
                const int n0 = j * 8;
                const unsigned br0 = sR[cur][n0 + g][kk + t    ];
                const unsigned br1 = sR[cur][n0 + g][kk + t + 4];
                const unsigned bi0 = sI[cur][n0 + g][kk + t    ];
                const unsigned bi1 = sI[cur][n0 + g][kk + t + 4];
                mma_tf32(accR[j], ar0, ar1, ar2, ar3, br0, br1);  // += R^T R
                mma_tf32(accR[j], ai0, ai1, ai2, ai3, bi0, bi1);  // += I^T I
                mma_tf32(accM[j], ar0, ar1, ar2, ar3, bi0, bi1);  // += R^T I
            }
        }

        // Store prefetched stage into the other buffer.
        if (st + 1 < NSTAGE) {
#pragma unroll
            for (int c = 0; c < 4; c++) {
                sR[nxt][dseg + 4 * c + 0][kloc] = f2tf(rv[c].x);
                sR[nxt][dseg + 4 * c + 1][kloc] = f2tf(rv[c].y);
                sR[nxt][dseg + 4 * c + 2][kloc] = f2tf(rv[c].z);
                sR[nxt][dseg + 4 * c + 3][kloc] = f2tf(rv[c].w);
                sI[nxt][dseg + 4 * c + 0][kloc] = f2tf(iv[c].x);
                sI[nxt][dseg + 4 * c + 1][kloc] = f2tf(iv[c].y);
                sI[nxt][dseg + 4 * c + 2][kloc] = f2tf(iv[c].z);
                sI[nxt][dseg + 4 * c + 3][kloc] = f2tf(iv[c].w);
            }
        }
        __syncthreads();
    }

    // ---- epilogue: write partials to scratch ----
    // C frag map: c0:(g,2t) c1:(g,2t+1) c2:(g+8,2t) c3:(g+8,2t+1)
    float* p = g_scratch + (long)((sp * NB + b) * 2) * (ND * ND);
#pragma unroll
    for (int j = 0; j < 8; j++) {
        const int n = j * 8 + 2 * t;
        const int mA = m0 + g;
        const int mB = m0 + g + 8;
        *(float2*)(p + mA * ND + n)            = make_float2(accR[j][0], accR[j][1]);
        *(float2*)(p + mB * ND + n)            = make_float2(accR[j][2], accR[j][3]);
        *(float2*)(p + ND * ND + mA * ND + n)  = make_float2(accM[j][0], accM[j][1]);
        *(float2*)(p + ND * ND + mB * ND + n)  = make_float2(accM[j][2], accM[j][3]);
    }
}

__global__ void reduce_kernel(float* __restrict__ out) {
    const int idx = blockIdx.x * blockDim.x + threadIdx.x;
    if (idx >= NB * ND * ND) return;
    const int b  = idx >> 12;
    const int ij = idx & 4095;
    const int i  = ij >> 6;
    const int j  = ij & 63;

    float sr = 0.0f, x = 0.0f, y = 0.0f;
#pragma unroll
    for (int sp = 0; sp < NSPLIT; sp++) {
        const float* p = g_scratch + (long)((sp * NB + b) * 2) * (ND * ND);
        sr += p[ij];
        x  += p[ND * ND + i * ND + j];
        y  += p[ND * ND + j * ND + i];
    }
    const float inv = 1.0f / (float)NS;
    out[idx]               = sr * inv;        // out_real [B,D,D]
    out[NB * ND * ND + idx] = (x - y) * inv;  // out_imag [B,D,D] (exact 0 diag)
}

extern "C" void kernel_launch(void* const* d_in, const int* in_sizes, int n_in,
                              void* d_out, int out_size) {
    const float* input_real = (const float*)d_in[0];
    const float* input_imag = (const float*)d_in[1];
    float* out = (float*)d_out;

    gram_kernel<<<NB * NSPLIT, 128>>>(input_real, input_imag);
    reduce_kernel<<<(NB * ND * ND + 255) / 256, 256>>>(out);

    (void)in_sizes; (void)n_in; (void)out_size;
}